// round 13
// baseline (speedup 1.0000x reference)
#include <cuda_runtime.h>
#include <cstdint>

#define NN    7680
#define NASM  256
#define CAPN  30
#define BSZ   64
#define NT    256

typedef unsigned long long ull;

__device__ int      g_total[NN];          // masked colsum (int), zeroed by memset
__device__ unsigned g_wbits[NN];          // bit c of row i: W_rec[i, p[i/30]*30+c] != 0
// TRANSPOSED half sums: element j=tid*30+q stored at [q*256 + tid]
__device__ float    g_half[2][BSZ][NN];

// ---- prep config ----
#define PNT      320
#define ASM_BLK  NASM                // 256 blocks: per-source-assembly colsum+wbits
#define WIN_BLK  (BSZ * 12)          // W_in: 64 samples * 6 chunks * 2 halves

// ---------------------------------------------------------------------------
__global__ __launch_bounds__(PNT)
void prep_kernel(const int* __restrict__ p, const int* __restrict__ s,
                 const float* __restrict__ W_in, const float* __restrict__ W_rec) {
    const int bid = blockIdx.x, tid = threadIdx.x;
    __shared__ int s_sh[BSZ];
    __shared__ int keep;
    if (bid < ASM_BLK) {
        // source assembly m: read its 30x30 W_rec tile at target columns,
        // pack wbits per row, accumulate integer column sums into g_total.
        if (tid >= 32) return;
        const int m = bid;
        const int pa = __ldg(&p[m]);
        const int lane = tid;
        int csum = 0;
        #pragma unroll
        for (int r = 0; r < CAPN; ++r) {
            int i = m * CAPN + r;
            float v = (lane < CAPN)
                ? __ldg(&W_rec[(size_t)i * NN + pa * CAPN + lane]) : 0.f;
            unsigned mask = __ballot_sync(0xFFFFFFFFu, v != 0.f) & 0x3FFFFFFFu;
            if (lane == 0) g_wbits[i] = mask;
            csum += (v != 0.f);
        }
        if (lane < CAPN) atomicAdd(&g_total[pa * CAPN + lane], csum);
    } else {
        // W_in 15-row half sums; coalesced float4 reads, transposed writes.
        int r = bid - ASM_BLK;
        int b = r / 12, rem = r % 12;
        int half = rem / 6, chunk = rem % 6;
        // parallel duplicate-sample vote (no serial scan)
        if (tid < BSZ) s_sh[tid] = __ldg(&s[tid]);
        if (tid == 0) keep = 1;
        __syncthreads();
        if (tid < b && s_sh[tid] == s_sh[b]) keep = 0;
        __syncthreads();
        if (!keep) return;
        const int sb = s_sh[b];
        const float4* base = (const float4*)(W_in + (size_t)sb * CAPN * NN)
                             + (size_t)(half * 15) * (NN / 4) + chunk * PNT + tid;
        float4 acc = {0.f, 0.f, 0.f, 0.f};
        #pragma unroll
        for (int rr = 0; rr < 15; ++rr) {
            float4 v = __ldg(&base[(size_t)rr * (NN / 4)]);
            acc.x += v.x; acc.y += v.y; acc.z += v.z; acc.w += v.w;
        }
        // transposed scatter: j -> (j%30)*256 + j/30
        int j0 = (chunk * PNT + tid) * 4;
        float* dst = g_half[half][b];
        float vv[4] = {acc.x, acc.y, acc.z, acc.w};
        #pragma unroll
        for (int z = 0; z < 4; ++z) {
            int j = j0 + z;
            dst[(j % CAPN) * 256 + (j / CAPN)] = vv[z];
        }
    }
}

// ---------------------------------------------------------------------------
__device__ __forceinline__ int block_scan_incl(int v, int* wsum, int tid) {
    int lane = tid & 31, w = tid >> 5;
    int x = v;
    #pragma unroll
    for (int off = 1; off < 32; off <<= 1) {
        int n = __shfl_up_sync(0xFFFFFFFFu, x, off);
        if (lane >= off) x += n;
    }
    if (lane == 31) wsum[w] = x;
    __syncthreads();
    if (tid < 8) {
        int y = wsum[tid];
        #pragma unroll
        for (int off = 1; off < 8; off <<= 1) {
            int n = __shfl_up_sync(0xFFu, y, off);
            if (tid >= off) y += n;
        }
        wsum[tid] = y;
    }
    __syncthreads();
    int r = x + (w ? wsum[w - 1] : 0);
    __syncthreads();
    return r;
}

// ---------------------------------------------------------------------------
// Chase: one 256-thread block per sample.
// ---------------------------------------------------------------------------
__global__ __launch_bounds__(NT)
void chase_kernel(const int* __restrict__ p, const int* __restrict__ s,
                  const int* __restrict__ kk, float* __restrict__ out) {
    __shared__ ull      cand[960];     // positive-score keys (unordered)
    __shared__ unsigned zmask[32];     // per-slot zero-column bitmask
    __shared__ int p_sh[NASM];
    __shared__ int s_sh[BSZ];
    __shared__ int bsrc_sh;
    __shared__ int active[CAPN];
    __shared__ int bases[32];
    __shared__ int slotcnt[32];
    __shared__ int slotlist[32 * CAPN];
    __shared__ int lh[8 * 32];         // 8 per-warp replicas x 31 bins
    __shared__ int wsum[8];
    __shared__ int sh[4];              // [0]=T [1]=n_gt [3]=nb
    __shared__ int ccnt;
    __shared__ int ov[NASM];

    const int tid  = threadIdx.x;
    const int wid  = tid >> 5;
    const int lane = tid & 31;
    const int b    = blockIdx.x;

    if (tid < NASM) p_sh[tid] = __ldg(&p[tid]);
    if (tid < BSZ)  s_sh[tid] = __ldg(&s[tid]);
    if (tid == 0)   bsrc_sh = b;
    lh[tid] = 0;
    __syncthreads();
    // parallel dedup vote
    if (tid < b && s_sh[tid] == s_sh[b]) atomicMin(&bsrc_sh, tid);
    __syncthreads();
    const int bsrc = bsrc_sh;

    // first-select scores: thread owns columns [tid*30, tid*30+30).
    // Transposed layout -> fully coalesced loads. Exact int sums.
    float sv[CAPN];
    {
        const float* h0 = g_half[0][bsrc];
        const float* h1 = g_half[1][bsrc];
        #pragma unroll
        for (int q = 0; q < CAPN; ++q)
            sv[q] = __ldg(&h0[q * 256 + tid]) + __ldg(&h1[q * 256 + tid]);
    }

    // ---- first k-WTA: exact int scores 0..30, per-warp histogram replicas ----
    #pragma unroll
    for (int q = 0; q < CAPN; ++q)
        atomicAdd(&lh[wid * 32 + (int)sv[q]], 1);
    __syncthreads();
    if (tid < 32) {
        int tot = 0;
        if (tid < 31) {
            #pragma unroll
            for (int w = 0; w < 8; ++w) tot += lh[w * 32 + tid];
        }
        int S = tot;                  // suffix sum: #{score >= tid}
        #pragma unroll
        for (int off = 1; off < 32; off <<= 1) {
            int tp = __shfl_down_sync(0xFFFFFFFFu, S, off);
            if (tid + off < 32) S += tp;
        }
        if (tid < 31 && S >= CAPN && S - tot < CAPN) {
            sh[0] = tid;              // threshold value T
            sh[1] = S - tot;          // n_gt = #{score > T}
        }
    }
    __syncthreads();
    {
        const int T = sh[0], n_gt = sh[1], need_eq = CAPN - n_gt;
        int cgt = 0, ceq = 0;
        #pragma unroll
        for (int q = 0; q < CAPN; ++q) {
            int val = (int)sv[q];
            cgt += (val > T); ceq += (val == T);
        }
        int pack = (cgt << 16) | ceq;
        int ex = block_scan_incl(pack, wsum, tid) - pack;
        int g_off = ex >> 16, e_off = ex & 0xFFFF;
        // contiguous per-thread ownership -> equal-value order == ascending j
        #pragma unroll
        for (int q = 0; q < CAPN; ++q) {
            int val = (int)sv[q];
            if (val > T) active[g_off++] = tid * CAPN + q;
            else if (val == T) {
                if (e_off < need_eq) active[n_gt + e_off] = tid * CAPN + q;
                e_off++;
            }
        }
    }
    __syncthreads();

    // ---- k[b] pointer-chasing steps ----
    const int steps = __ldg(&kk[b]);
    for (int t = 0; t < steps; ++t) {
        // Phase A: warp 0 builds tmask/fallback/bases/slots (register-only).
        if (wid == 0) {
            int i_act = -1, a = 0;
            if (lane < CAPN) { i_act = active[lane]; a = p_sh[i_act / CAPN]; }
            unsigned tm[8];
            #pragma unroll
            for (int w = 0; w < 8; ++w) {
                unsigned mm = (lane < CAPN && (a >> 5) == w) ? (1u << (a & 31)) : 0u;
                tm[w] = __reduce_or_sync(0xFFFFFFFFu, mm);
            }
            // fallback = smallest non-targeted assembly (zero-tie semantics:
            // together with targeted assemblies' own zero columns this covers
            // the globally smallest-index zero-score columns)
            bool done = false;
            #pragma unroll
            for (int w = 0; w < 8; ++w) {
                if (!done && tm[w] != 0xFFFFFFFFu) {
                    tm[w] |= (1u << (__ffs(~tm[w]) - 1));
                    done = true;
                }
            }
            int nb = 0;
            #pragma unroll
            for (int w = 0; w < 8; ++w) nb += __popc(tm[w]);
            if (lane == 0) sh[3] = nb;
            if (lane < nb) {                      // lane-th set bit, ascending
                int rem = lane, base = -1;
                #pragma unroll
                for (int w = 0; w < 8; ++w) {
                    int pc = __popc(tm[w]);
                    if (base < 0) {
                        if (rem < pc) {
                            unsigned x = tm[w];
                            for (int k2 = 0; k2 < rem; ++k2) x &= x - 1;
                            base = w * 32 + __ffs(x) - 1;
                        } else rem -= pc;
                    }
                }
                bases[lane] = base;
                slotcnt[lane] = 0;
            }
            __syncwarp();
            int slot = 32 + lane;                 // unique for inactive lanes
            if (lane < CAPN) {
                int w = a >> 5, bit = a & 31;
                slot = __popc(tm[w] & ((1u << bit) - 1u));
                #pragma unroll
                for (int ww = 0; ww < 8; ++ww)
                    if (ww < w) slot += __popc(tm[ww]);
            }
            unsigned mmask = __match_any_sync(0xFFFFFFFFu, slot);
            if (lane < CAPN) {
                int rank = __popc(mmask & ((1u << lane) - 1u));
                slotlist[slot * CAPN + rank] = i_act;
                if (rank == 0) slotcnt[slot] = __popc(mmask);
            }
        } else if (tid == 32) {
            ccnt = 0;
        }
        __syncthreads();
        const int nb = sh[3];

        // Phase B: per-slot gather; compact POSITIVE keys only. Zero columns
        // recorded as per-slot bitmasks for the rare zero-fill path.
        for (int sI = wid; sI < nb; sI += 8) {
            int m = slotcnt[sI];
            unsigned rowm = (lane < m)
                ? __ldg(&g_wbits[slotlist[sI * CAPN + lane]]) : 0u;
            int cnt = 0;
            for (int u = 0; u < m; ++u)
                cnt += (__shfl_sync(0xFFFFFFFFu, rowm, u) >> lane) & 1;
            bool isz  = (lane < CAPN) && (cnt == 0);
            bool ispp = (lane < CAPN) && (cnt > 0);
            unsigned zb = __ballot_sync(0xFFFFFFFFu, isz);
            unsigned pb = __ballot_sync(0xFFFFFFFFu, ispp);
            if (lane == 0) zmask[sI] = zb;
            int basep = 0;
            if (lane == 0 && pb) basep = atomicAdd(&ccnt, __popc(pb));
            basep = __shfl_sync(0xFFFFFFFFu, basep, 0);
            if (ispp) {
                int e = sI * CAPN + lane;
                int j = bases[sI] * CAPN + lane;
                // inv identical bits to 1/max(float colsum,1e-6): colsum is an
                // exact small int either way.
                float inv = 1.0f / fmaxf((float)__ldg(&g_total[j]), 1e-6f);
                float scv = (float)cnt * inv;     // == ref column sum
                int idx = basep + __popc(pb & ((1u << lane) - 1u));
                cand[idx] = ((ull)__float_as_uint(scv) << 32) | (unsigned)(~e);
            }
        }
        __syncthreads();
        const int npos = ccnt;

        // Rank: broadcast all-pairs. Keys distinct (contain ~e), so
        // rank == exact (value desc, index asc) position == top_k order.
        {
            ull kt[4];
            int nk = 0;
            #pragma unroll
            for (int q = 0; q < 4; ++q) {
                int idx = tid + q * NT;
                if (idx < npos) kt[nk++] = cand[idx];
            }
            if (nk) {
                int rk[4] = {0, 0, 0, 0};
                for (int i = 0; i < npos; ++i) {
                    ull v = cand[i];
                    #pragma unroll
                    for (int q = 0; q < 4; ++q)
                        if (q < nk) rk[q] += (v > kt[q]);
                }
                #pragma unroll
                for (int q = 0; q < 4; ++q) {
                    if (q < nk && rk[q] < CAPN) {
                        int e = (int)(~(unsigned)kt[q]);
                        active[rk[q]] = bases[e / CAPN] * CAPN + (e % CAPN);
                    }
                }
            }
        }
        // Zero-fill (npos < 30): remaining winners = smallest-index zero-score
        // columns, slot-ascending (== j ascending; bases sorted) then bit-asc.
        if (npos < CAPN) {
            __syncthreads();          // ranks written before filling tail
            if (wid == 0) {
                int zc = (lane < nb) ? __popc(zmask[lane]) : 0;
                int ex = zc;
                #pragma unroll
                for (int off = 1; off < 32; off <<= 1) {
                    int n = __shfl_up_sync(0xFFFFFFFFu, ex, off);
                    if (lane >= off) ex += n;
                }
                ex -= zc;             // zeros in slots before mine
                if (lane < nb) {
                    unsigned zb = zmask[lane];
                    int pos = npos + ex;
                    while (zb && pos < CAPN) {
                        int bit = __ffs(zb) - 1;
                        zb &= zb - 1;
                        active[pos++] = bases[lane] * CAPN + bit;
                    }
                }
            }
        }
        __syncthreads();
    }

    // ---- overlaps + first-max argmax + one-hot ----
    ov[tid] = 0;
    if (tid == 0) sh[0] = -1;
    __syncthreads();
    if (tid < CAPN) atomicAdd(&ov[active[tid] / CAPN], 1);
    __syncthreads();
    atomicMax(&sh[0], (ov[tid] << 8) | (255 - tid));   // ties -> smallest id
    __syncthreads();
    const int best = 255 - (sh[0] & 255);
    out[b * NASM + tid] = (tid == best) ? 1.0f : 0.0f;
}

// ---------------------------------------------------------------------------
extern "C" void kernel_launch(void* const* d_in, const int* in_sizes, int n_in,
                              void* d_out, int out_size) {
    const int*   p     = (const int*)d_in[0];   // [256]
    const int*   s     = (const int*)d_in[1];   // [64]
    const int*   kk    = (const int*)d_in[2];   // [64]
    const float* W_in  = (const float*)d_in[3]; // [7680,7680]
    const float* W_rec = (const float*)d_in[4]; // [7680,7680]
    float* out = (float*)d_out;                 // [64,256]

    void* total_addr = nullptr;
    cudaGetSymbolAddress(&total_addr, g_total);
    cudaMemsetAsync(total_addr, 0, NN * sizeof(int));
    prep_kernel<<<ASM_BLK + WIN_BLK, PNT>>>(p, s, W_in, W_rec);
    chase_kernel<<<BSZ, NT>>>(p, s, kk, out);
}

// round 14
// speedup vs baseline: 1.2457x; 1.2457x over previous
#include <cuda_runtime.h>
#include <cstdint>

#define NN    7680
#define NASM  256
#define CAPN  30
#define BSZ   64
#define NT    256

typedef unsigned long long ull;

__device__ int      g_total[NN];          // masked colsum (int), zeroed by memset
__device__ unsigned g_wbits[NN];          // bit c of row i: W_rec[i, p[i/30]*30+c] != 0
// TRANSPOSED half sums: element j=tid*30+q stored at [q*256 + tid]
__device__ float    g_half[2][BSZ][NN];

// ---- prep config ----
#define PNT      320
#define ASM_BLK  NASM                // 256 blocks: per-source-assembly colsum+wbits
#define WIN_BLK  (BSZ * 12)          // W_in: 64 samples * 6 chunks * 2 halves

// ---------------------------------------------------------------------------
__global__ __launch_bounds__(PNT)
void prep_kernel(const int* __restrict__ p, const int* __restrict__ s,
                 const float* __restrict__ W_in, const float* __restrict__ W_rec) {
    const int bid = blockIdx.x, tid = threadIdx.x;
    __shared__ int s_sh[BSZ];
    __shared__ int keep;
    if (bid < ASM_BLK) {
        // source assembly m: read its 30x30 W_rec tile at target columns,
        // pack wbits per row, accumulate integer column sums into g_total.
        if (tid >= 32) return;
        const int m = bid;
        const int pa = __ldg(&p[m]);
        const int lane = tid;
        int csum = 0;
        #pragma unroll
        for (int r = 0; r < CAPN; ++r) {
            int i = m * CAPN + r;
            float v = (lane < CAPN)
                ? __ldg(&W_rec[(size_t)i * NN + pa * CAPN + lane]) : 0.f;
            unsigned mask = __ballot_sync(0xFFFFFFFFu, v != 0.f) & 0x3FFFFFFFu;
            if (lane == 0) g_wbits[i] = mask;
            csum += (v != 0.f);
        }
        if (lane < CAPN) atomicAdd(&g_total[pa * CAPN + lane], csum);
    } else {
        // W_in 15-row half sums; coalesced float4 reads, transposed writes.
        int r = bid - ASM_BLK;
        int b = r / 12, rem = r % 12;
        int half = rem / 6, chunk = rem % 6;
        // parallel duplicate-sample vote (no serial scan)
        if (tid < BSZ) s_sh[tid] = __ldg(&s[tid]);
        if (tid == 0) keep = 1;
        __syncthreads();
        if (tid < b && s_sh[tid] == s_sh[b]) keep = 0;
        __syncthreads();
        if (!keep) return;
        const int sb = s_sh[b];
        const float4* base = (const float4*)(W_in + (size_t)sb * CAPN * NN)
                             + (size_t)(half * 15) * (NN / 4) + chunk * PNT + tid;
        float4 acc = {0.f, 0.f, 0.f, 0.f};
        #pragma unroll
        for (int rr = 0; rr < 15; ++rr) {
            float4 v = __ldg(&base[(size_t)rr * (NN / 4)]);
            acc.x += v.x; acc.y += v.y; acc.z += v.z; acc.w += v.w;
        }
        // transposed scatter: j -> (j%30)*256 + j/30
        int j0 = (chunk * PNT + tid) * 4;
        float* dst = g_half[half][b];
        float vv[4] = {acc.x, acc.y, acc.z, acc.w};
        #pragma unroll
        for (int z = 0; z < 4; ++z) {
            int j = j0 + z;
            dst[(j % CAPN) * 256 + (j / CAPN)] = vv[z];
        }
    }
}

// ---------------------------------------------------------------------------
__device__ __forceinline__ int block_scan_incl(int v, int* wsum, int tid) {
    int lane = tid & 31, w = tid >> 5;
    int x = v;
    #pragma unroll
    for (int off = 1; off < 32; off <<= 1) {
        int n = __shfl_up_sync(0xFFFFFFFFu, x, off);
        if (lane >= off) x += n;
    }
    if (lane == 31) wsum[w] = x;
    __syncthreads();
    if (tid < 8) {
        int y = wsum[tid];
        #pragma unroll
        for (int off = 1; off < 8; off <<= 1) {
            int n = __shfl_up_sync(0xFFu, y, off);
            if (tid >= off) y += n;
        }
        wsum[tid] = y;
    }
    __syncthreads();
    int r = x + (w ? wsum[w - 1] : 0);
    __syncthreads();
    return r;
}

// ---------------------------------------------------------------------------
// Chase: one 256-thread block per sample.
// ---------------------------------------------------------------------------
__global__ __launch_bounds__(NT)
void chase_kernel(const int* __restrict__ p, const int* __restrict__ s,
                  const int* __restrict__ kk, float* __restrict__ out) {
    __shared__ ull      cand[960];     // compact positive-score keys
    __shared__ ull      cand2[960];    // threshold-bin keys
    __shared__ unsigned zmask[32];     // per-slot zero-column bitmask
    __shared__ int hist8[8 * 256];
    __shared__ int p_sh[NASM];
    __shared__ int s_sh[BSZ];
    __shared__ int bsrc_sh;
    __shared__ int active[CAPN];
    __shared__ int bases[32];
    __shared__ int slotcnt[32];
    __shared__ int slotlist[32 * CAPN];
    __shared__ int lh[8 * 32];         // 8 per-warp replicas x 31 bins
    __shared__ int wsum[8];
    __shared__ int sh[4];              // [0]=B/T [1]=n_gt [2]=emit [3]=nb
    __shared__ int ccnt, c2cnt;
    __shared__ int ov[NASM];

    const int tid  = threadIdx.x;
    const int wid  = tid >> 5;
    const int lane = tid & 31;
    const int b    = blockIdx.x;

    if (tid < NASM) p_sh[tid] = __ldg(&p[tid]);
    if (tid < BSZ)  s_sh[tid] = __ldg(&s[tid]);
    if (tid == 0)   bsrc_sh = b;
    lh[tid] = 0;
    __syncthreads();
    // parallel dedup vote
    if (tid < b && s_sh[tid] == s_sh[b]) atomicMin(&bsrc_sh, tid);
    __syncthreads();
    const int bsrc = bsrc_sh;

    // first-select scores: thread owns columns [tid*30, tid*30+30).
    // Transposed layout -> fully coalesced loads. Exact int sums.
    float sv[CAPN];
    {
        const float* h0 = g_half[0][bsrc];
        const float* h1 = g_half[1][bsrc];
        #pragma unroll
        for (int q = 0; q < CAPN; ++q)
            sv[q] = __ldg(&h0[q * 256 + tid]) + __ldg(&h1[q * 256 + tid]);
    }

    // ---- first k-WTA: exact int scores 0..30, per-warp histogram replicas ----
    #pragma unroll
    for (int q = 0; q < CAPN; ++q)
        atomicAdd(&lh[wid * 32 + (int)sv[q]], 1);
    __syncthreads();
    if (tid < 32) {
        int tot = 0;
        if (tid < 31) {
            #pragma unroll
            for (int w = 0; w < 8; ++w) tot += lh[w * 32 + tid];
        }
        int S = tot;                  // suffix sum: #{score >= tid}
        #pragma unroll
        for (int off = 1; off < 32; off <<= 1) {
            int tp = __shfl_down_sync(0xFFFFFFFFu, S, off);
            if (tid + off < 32) S += tp;
        }
        if (tid < 31 && S >= CAPN && S - tot < CAPN) {
            sh[0] = tid;              // threshold value T
            sh[1] = S - tot;          // n_gt = #{score > T}
        }
    }
    __syncthreads();
    {
        const int T = sh[0], n_gt = sh[1], need_eq = CAPN - n_gt;
        int cgt = 0, ceq = 0;
        #pragma unroll
        for (int q = 0; q < CAPN; ++q) {
            int val = (int)sv[q];
            cgt += (val > T); ceq += (val == T);
        }
        int pack = (cgt << 16) | ceq;
        int ex = block_scan_incl(pack, wsum, tid) - pack;
        int g_off = ex >> 16, e_off = ex & 0xFFFF;
        // contiguous per-thread ownership -> equal-value order == ascending j
        #pragma unroll
        for (int q = 0; q < CAPN; ++q) {
            int val = (int)sv[q];
            if (val > T) active[g_off++] = tid * CAPN + q;
            else if (val == T) {
                if (e_off < need_eq) active[n_gt + e_off] = tid * CAPN + q;
                e_off++;
            }
        }
    }
    __syncthreads();

    // ---- k[b] pointer-chasing steps ----
    const int steps = __ldg(&kk[b]);
    for (int t = 0; t < steps; ++t) {
        // Phase A: warp 0 builds tmask/fallback/bases/slots (register-only);
        // warps 1-7 zero the histogram replicas + counters concurrently.
        if (wid == 0) {
            int i_act = -1, a = 0;
            if (lane < CAPN) { i_act = active[lane]; a = p_sh[i_act / CAPN]; }
            unsigned tm[8];
            #pragma unroll
            for (int w = 0; w < 8; ++w) {
                unsigned mm = (lane < CAPN && (a >> 5) == w) ? (1u << (a & 31)) : 0u;
                tm[w] = __reduce_or_sync(0xFFFFFFFFu, mm);
            }
            // fallback = smallest non-targeted assembly (zero-tie semantics:
            // together with targeted assemblies' own zero columns this covers
            // the globally smallest-index zero-score columns)
            bool done = false;
            #pragma unroll
            for (int w = 0; w < 8; ++w) {
                if (!done && tm[w] != 0xFFFFFFFFu) {
                    tm[w] |= (1u << (__ffs(~tm[w]) - 1));
                    done = true;
                }
            }
            int nb = 0;
            #pragma unroll
            for (int w = 0; w < 8; ++w) nb += __popc(tm[w]);
            if (lane == 0) sh[3] = nb;
            if (lane < nb) {                      // lane-th set bit, ascending
                int rem = lane, base = -1;
                #pragma unroll
                for (int w = 0; w < 8; ++w) {
                    int pc = __popc(tm[w]);
                    if (base < 0) {
                        if (rem < pc) {
                            unsigned x = tm[w];
                            for (int k2 = 0; k2 < rem; ++k2) x &= x - 1;
                            base = w * 32 + __ffs(x) - 1;
                        } else rem -= pc;
                    }
                }
                bases[lane] = base;
                slotcnt[lane] = 0;
            }
            __syncwarp();
            int slot = 32 + lane;                 // unique for inactive lanes
            if (lane < CAPN) {
                int w = a >> 5, bit = a & 31;
                slot = __popc(tm[w] & ((1u << bit) - 1u));
                #pragma unroll
                for (int ww = 0; ww < 8; ++ww)
                    if (ww < w) slot += __popc(tm[ww]);
            }
            unsigned mmask = __match_any_sync(0xFFFFFFFFu, slot);
            if (lane < CAPN) {
                int rank = __popc(mmask & ((1u << lane) - 1u));
                slotlist[slot * CAPN + rank] = i_act;
                if (rank == 0) slotcnt[slot] = __popc(mmask);
            }
        } else {
            if (tid == 32) { sh[2] = 0; ccnt = 0; c2cnt = 0; }
            // vectorized hist zeroing: 512 int4 over 224 threads
            int4* h4 = (int4*)hist8;
            for (int i = tid - 32; i < 512; i += NT - 32)
                h4[i] = make_int4(0, 0, 0, 0);
        }
        __syncthreads();
        const int nb = sh[3];

        // Phase B: shfl-broadcast gather; compact POSITIVES only (plus zmask).
        // Histogram only positive scores (zeros were ~70% of all atomics).
        for (int sI = wid; sI < nb; sI += 8) {
            int m = slotcnt[sI];
            unsigned rowm = (lane < m)
                ? __ldg(&g_wbits[slotlist[sI * CAPN + lane]]) : 0u;
            int cnt = 0;
            for (int u = 0; u < m; ++u)
                cnt += (__shfl_sync(0xFFFFFFFFu, rowm, u) >> lane) & 1;
            bool ispp = (lane < CAPN) && (cnt > 0);
            unsigned pb = __ballot_sync(0xFFFFFFFFu, ispp);
            unsigned zb = __ballot_sync(0xFFFFFFFFu, (lane < CAPN) && (cnt == 0));
            if (lane == 0) zmask[sI] = zb;
            int basep = 0;
            if (lane == 0 && pb) basep = atomicAdd(&ccnt, __popc(pb));
            basep = __shfl_sync(0xFFFFFFFFu, basep, 0);
            if (ispp) {
                int e = sI * CAPN + lane;
                int j = bases[sI] * CAPN + lane;
                // inv identical bits to 1/max(float colsum,1e-6): colsum is an
                // exact small int either way.
                float inv = 1.0f / fmaxf((float)__ldg(&g_total[j]), 1e-6f);
                float scv = (float)cnt * inv;     // == ref column sum
                int idx = basep + __popc(pb & ((1u << lane) - 1u));
                cand[idx] = ((ull)__float_as_uint(scv) << 32) | (unsigned)(~e);
                atomicAdd(&hist8[wid * 256 + min(255, (int)(scv * 256.f))], 1);
            }
        }
        __syncthreads();
        const int npos = ccnt;

        if (npos >= CAPN) {
            // Phase C: warp 0 finds threshold bin B via suffix scan (positives)
            if (wid == 0) {
                int lvals[8], lsum = 0;
                #pragma unroll
                for (int q = 0; q < 8; ++q) {
                    int bb = 255 - (lane * 8 + q);
                    int tot = 0;
                    #pragma unroll
                    for (int w = 0; w < 8; ++w) tot += hist8[w * 256 + bb];
                    lvals[q] = tot; lsum += tot;
                }
                int scn = lsum;
                #pragma unroll
                for (int off = 1; off < 32; off <<= 1) {
                    int n = __shfl_up_sync(0xFFFFFFFFu, scn, off);
                    if (lane >= off) scn += n;
                }
                int acc = scn - lsum;     // #elems in bins above my group
                #pragma unroll
                for (int q = 0; q < 8; ++q) {
                    int S = acc + lvals[q];
                    if (S >= CAPN && acc < CAPN) {
                        sh[0] = 255 - (lane * 8 + q);   // threshold bin B
                        sh[1] = acc;                    // n_gt
                    }
                    acc = S;
                }
            }
            __syncthreads();
            const int B = sh[0], ngt = sh[1], k_rem = CAPN - ngt;

            // Phase D: scan COMPACT positive list only (~npos entries).
            // Bins > B emit unordered (kWTA result is a set); bin B -> cand2.
            for (int idx = tid; idx < npos; idx += NT) {
                ull k2 = cand[idx];
                float scv = __uint_as_float((unsigned)(k2 >> 32));
                int bin = min(255, (int)(scv * 256.f));
                if (bin > B) {
                    int e = (int)(~(unsigned)k2);
                    active[atomicAdd(&sh[2], 1)] =
                        bases[e / CAPN] * CAPN + (e % CAPN);
                } else if (bin == B) {
                    cand2[atomicAdd(&c2cnt, 1)] = k2;
                }
            }
            __syncthreads();

            // Phase E: small all-pairs exact rank over threshold bin.
            // Keys distinct (contain ~e): key desc == (value desc, index asc).
            const int L = c2cnt;
            if (L <= NT) {
                if (tid < L) {
                    ull kt = cand2[tid];
                    int rank = 0;
                    for (int i = 0; i < L; ++i) rank += (cand2[i] > kt);
                    if (rank < k_rem) {
                        int e = (int)(~(unsigned)kt);
                        active[ngt + rank] =
                            bases[e / CAPN] * CAPN + (e % CAPN);
                    }
                }
                __syncthreads();
            } else {
                // rare fallback: serial rounds on warp 0
                if (wid == 0) {
                    for (int r2 = 0; r2 < k_rem; ++r2) {
                        ull lmax = 0ull;
                        for (int idx = lane; idx < L; idx += 32)
                            lmax = max(lmax, cand2[idx]);
                        unsigned Mhi = __reduce_max_sync(0xFFFFFFFFu, (unsigned)(lmax >> 32));
                        unsigned lo  = ((unsigned)(lmax >> 32) == Mhi) ? (unsigned)lmax : 0u;
                        unsigned Mlo = __reduce_max_sync(0xFFFFFFFFu, lo);
                        ull wk = ((ull)Mhi << 32) | Mlo;
                        for (int idx = lane; idx < L; idx += 32)
                            if (cand2[idx] == wk) cand2[idx] = 0ull;
                        if (lane == 0) {
                            int e = (int)(~Mlo);
                            active[ngt + r2] =
                                bases[e / CAPN] * CAPN + (e % CAPN);
                        }
                        __syncwarp();
                    }
                }
                __syncthreads();
            }
        } else {
            // npos < 30: every positive wins (set semantics -> unordered).
            for (int idx = tid; idx < npos; idx += NT) {
                int e = (int)(~(unsigned)cand[idx]);
                active[idx] = bases[e / CAPN] * CAPN + (e % CAPN);
            }
            // zero-fill remaining with smallest-index zero-score columns,
            // slot-ascending (== j ascending; bases sorted) then bit-asc.
            if (wid == 0) {
                int zc = (lane < nb) ? __popc(zmask[lane]) : 0;
                int ex = zc;
                #pragma unroll
                for (int off = 1; off < 32; off <<= 1) {
                    int n = __shfl_up_sync(0xFFFFFFFFu, ex, off);
                    if (lane >= off) ex += n;
                }
                ex -= zc;             // zeros in slots before mine
                if (lane < nb) {
                    unsigned zb = zmask[lane];
                    int pos = npos + ex;
                    while (zb && pos < CAPN) {
                        int bit = __ffs(zb) - 1;
                        zb &= zb - 1;
                        active[pos++] = bases[lane] * CAPN + bit;
                    }
                }
            }
            __syncthreads();
        }
    }

    // ---- overlaps + first-max argmax + one-hot ----
    ov[tid] = 0;
    if (tid == 0) sh[0] = -1;
    __syncthreads();
    if (tid < CAPN) atomicAdd(&ov[active[tid] / CAPN], 1);
    __syncthreads();
    atomicMax(&sh[0], (ov[tid] << 8) | (255 - tid));   // ties -> smallest id
    __syncthreads();
    const int best = 255 - (sh[0] & 255);
    out[b * NASM + tid] = (tid == best) ? 1.0f : 0.0f;
}

// ---------------------------------------------------------------------------
extern "C" void kernel_launch(void* const* d_in, const int* in_sizes, int n_in,
                              void* d_out, int out_size) {
    const int*   p     = (const int*)d_in[0];   // [256]
    const int*   s     = (const int*)d_in[1];   // [64]
    const int*   kk    = (const int*)d_in[2];   // [64]
    const float* W_in  = (const float*)d_in[3]; // [7680,7680]
    const float* W_rec = (const float*)d_in[4]; // [7680,7680]
    float* out = (float*)d_out;                 // [64,256]

    void* total_addr = nullptr;
    cudaGetSymbolAddress(&total_addr, g_total);
    cudaMemsetAsync(total_addr, 0, NN * sizeof(int));
    prep_kernel<<<ASM_BLK + WIN_BLK, PNT>>>(p, s, W_in, W_rec);
    chase_kernel<<<BSZ, NT>>>(p, s, kk, out);
}